// round 1
// baseline (speedup 1.0000x reference)
#include <cuda_runtime.h>
#include <cuda_fp16.h>
#include <mma.h>
#include <cstdint>

using namespace nvcuda;

// Problem shape (fixed by the dataset)
#define Bb 8
#define Ss 2048
#define Dd 768
#define Oo 768
constexpr float SCALE = 0.125f;  // 1/sqrt(64), hardcoded in reference

constexpr size_t N_X   = (size_t)Bb * Ss * Dd;       // 12,582,912
constexpr size_t N_W   = (size_t)3 * Dd * Oo;        // 1,769,472
constexpr size_t N_QKV = (size_t)Bb * Ss * Oo;       // per-matrix 12,582,912
constexpr size_t N_SC  = (size_t)Bb * Ss * Ss;       // 33,554,432

// Scratch (static device globals — no runtime allocation)
__device__ __half g_x16[N_X];
__device__ __half g_w16[N_W];
__device__ __half g_qkv[3 * N_QKV];   // Q | K | V, fp16
__device__ float  g_scores[N_SC];     // QK^T * scale, fp32
__device__ __half g_probs[N_SC];      // softmax(QK^T), fp16

// ---------------------------------------------------------------------------
// fp32 -> fp16 convert
// ---------------------------------------------------------------------------
__global__ void cvt_f2h(const float* __restrict__ in, __half* __restrict__ out, size_t n) {
    size_t i = (size_t)blockIdx.x * blockDim.x + threadIdx.x;
    size_t stride = (size_t)gridDim.x * blockDim.x;
    for (; i < n; i += stride) out[i] = __float2half(in[i]);
}

// ---------------------------------------------------------------------------
// Tiled WMMA GEMM:  C = scale * A @ op(B)
//   A: [M,K] fp16 row-major, lda
//   B: BT=false -> [K,N] row-major (ldb);  BT=true -> [N,K] row-major (ldb), used as B^T
//   C: HALF_OUT ? fp16 : fp32, row-major ldc
//   blockIdx.z selects batch via the *Stride offsets.
// Block tile 128x128x32, 256 threads (8 warps), warp tile 32x64.
// ---------------------------------------------------------------------------
template <bool BT, bool HALF_OUT>
__global__ void __launch_bounds__(256)
gemm_wmma(const __half* __restrict__ Ag, const __half* __restrict__ Bg,
          void* __restrict__ Cg,
          int M, int N, int K, int lda, int ldb, int ldc, float scale,
          size_t aStride, size_t bStride, size_t cStride)
{
    constexpr int BM = 128, BN = 128, BK = 32;
    constexpr int BS_ROWS = BT ? BN : BK;
    constexpr int BS_COLS = BT ? (BK + 8) : (BN + 8);

    __shared__ __half As[BM][BK + 8];
    __shared__ __half Bs[BS_ROWS][BS_COLS];
    __shared__ float  stage[8][16 * 16];

    const int tid    = threadIdx.x;
    const int warpId = tid >> 5;
    const int lane   = tid & 31;
    const int bm = blockIdx.y * BM;
    const int bn = blockIdx.x * BN;

    const __half* A = Ag + (size_t)blockIdx.z * aStride;
    const __half* Bp = Bg + (size_t)blockIdx.z * bStride;

    const int warpM = warpId & 3;   // 0..3 -> 4*32 = 128 rows
    const int warpN = warpId >> 2;  // 0..1 -> 2*64 = 128 cols

    wmma::fragment<wmma::accumulator, 16, 16, 16, float> acc[2][4];
    #pragma unroll
    for (int fm = 0; fm < 2; fm++)
        #pragma unroll
        for (int fn = 0; fn < 4; fn++)
            wmma::fill_fragment(acc[fm][fn], 0.0f);

    for (int k0 = 0; k0 < K; k0 += BK) {
        // --- load A tile [BM x BK] (float4 = 8 halves per load) ---
        #pragma unroll
        for (int i = tid; i < (BM * BK) / 8; i += 256) {
            int row = i >> 2;            // / (BK/8)
            int cc  = (i & 3) << 3;
            *(float4*)&As[row][cc] =
                *(const float4*)&A[(size_t)(bm + row) * lda + k0 + cc];
        }
        // --- load B tile ---
        if (!BT) {
            #pragma unroll
            for (int i = tid; i < (BK * BN) / 8; i += 256) {
                int row = i >> 4;        // / (BN/8)
                int cc  = (i & 15) << 3;
                *(float4*)&Bs[row][cc] =
                    *(const float4*)&Bp[(size_t)(k0 + row) * ldb + bn + cc];
            }
        } else {
            #pragma unroll
            for (int i = tid; i < (BN * BK) / 8; i += 256) {
                int row = i >> 2;
                int cc  = (i & 3) << 3;
                *(float4*)&Bs[row][cc] =
                    *(const float4*)&Bp[(size_t)(bn + row) * ldb + k0 + cc];
            }
        }
        __syncthreads();

        #pragma unroll
        for (int kk = 0; kk < BK; kk += 16) {
            wmma::fragment<wmma::matrix_a, 16, 16, 16, __half, wmma::row_major> af[2];
            #pragma unroll
            for (int fm = 0; fm < 2; fm++)
                wmma::load_matrix_sync(af[fm], &As[warpM * 32 + fm * 16][kk], BK + 8);

            if (!BT) {
                #pragma unroll
                for (int fn = 0; fn < 4; fn++) {
                    wmma::fragment<wmma::matrix_b, 16, 16, 16, __half, wmma::row_major> bf;
                    wmma::load_matrix_sync(bf, &Bs[kk][warpN * 64 + fn * 16], BN + 8);
                    #pragma unroll
                    for (int fm = 0; fm < 2; fm++)
                        wmma::mma_sync(acc[fm][fn], af[fm], bf, acc[fm][fn]);
                }
            } else {
                #pragma unroll
                for (int fn = 0; fn < 4; fn++) {
                    wmma::fragment<wmma::matrix_b, 16, 16, 16, __half, wmma::col_major> bf;
                    wmma::load_matrix_sync(bf, &Bs[warpN * 64 + fn * 16][kk], BK + 8);
                    #pragma unroll
                    for (int fm = 0; fm < 2; fm++)
                        wmma::mma_sync(acc[fm][fn], af[fm], bf, acc[fm][fn]);
                }
            }
        }
        __syncthreads();
    }

    // --- epilogue ---
    #pragma unroll
    for (int fm = 0; fm < 2; fm++) {
        #pragma unroll
        for (int fn = 0; fn < 4; fn++) {
            #pragma unroll
            for (int e = 0; e < acc[fm][fn].num_elements; e++)
                acc[fm][fn].x[e] *= scale;

            int r0 = bm + warpM * 32 + fm * 16;
            int c0 = bn + warpN * 64 + fn * 16;

            if (!HALF_OUT) {
                float* Cf = (float*)Cg + (size_t)blockIdx.z * cStride;
                wmma::store_matrix_sync(&Cf[(size_t)r0 * ldc + c0], acc[fm][fn],
                                        ldc, wmma::mem_row_major);
            } else {
                __half* Ch = (__half*)Cg + (size_t)blockIdx.z * cStride;
                wmma::store_matrix_sync(stage[warpId], acc[fm][fn], 16, wmma::mem_row_major);
                __syncwarp();
                int rr = lane >> 1;
                int cc = (lane & 1) * 8;
                __half tmp[8];
                #pragma unroll
                for (int j = 0; j < 8; j++)
                    tmp[j] = __float2half(stage[warpId][rr * 16 + cc + j]);
                *(float4*)&Ch[(size_t)(r0 + rr) * ldc + c0 + cc] = *(float4*)tmp;
                __syncwarp();
            }
        }
    }
}

// ---------------------------------------------------------------------------
// Row softmax: scores fp32 [rows x 2048] -> probs fp16
// ---------------------------------------------------------------------------
__device__ __forceinline__ float warpMax(float v) {
    #pragma unroll
    for (int o = 16; o; o >>= 1) v = fmaxf(v, __shfl_xor_sync(0xffffffffu, v, o));
    return v;
}
__device__ __forceinline__ float warpSum(float v) {
    #pragma unroll
    for (int o = 16; o; o >>= 1) v += __shfl_xor_sync(0xffffffffu, v, o);
    return v;
}

__global__ void __launch_bounds__(256)
softmax_rows(const float* __restrict__ s, __half* __restrict__ p)
{
    const size_t row = blockIdx.x;
    const float* sr = s + row * Ss;
    __half* pr = p + row * Ss;
    const int tid = threadIdx.x;
    const int warp = tid >> 5, lane = tid & 31;

    float vals[8];
    float mx = -3.0e38f;
    #pragma unroll
    for (int j = 0; j < 8; j++) {
        vals[j] = sr[tid + j * 256];
        mx = fmaxf(mx, vals[j]);
    }
    __shared__ float redm[8], reds[8];
    mx = warpMax(mx);
    if (lane == 0) redm[warp] = mx;
    __syncthreads();
    float m = redm[0];
    #pragma unroll
    for (int i = 1; i < 8; i++) m = fmaxf(m, redm[i]);

    float sum = 0.0f;
    #pragma unroll
    for (int j = 0; j < 8; j++) {
        vals[j] = __expf(vals[j] - m);
        sum += vals[j];
    }
    sum = warpSum(sum);
    if (lane == 0) reds[warp] = sum;
    __syncthreads();
    float tot = 0.0f;
    #pragma unroll
    for (int i = 0; i < 8; i++) tot += reds[i];
    float inv = 1.0f / tot;

    #pragma unroll
    for (int j = 0; j < 8; j++)
        pr[tid + j * 256] = __float2half(vals[j] * inv);
}

// ---------------------------------------------------------------------------
// Launch
// ---------------------------------------------------------------------------
extern "C" void kernel_launch(void* const* d_in, const int* in_sizes, int n_in,
                              void* d_out, int out_size)
{
    const float* x = (const float*)d_in[0];
    const float* w = (const float*)d_in[1];
    // Defensive: metadata order is (x, kernel); swap if sizes say otherwise.
    if (n_in >= 2 && in_sizes[0] == (int)N_W && in_sizes[1] == (int)N_X) {
        const float* t = x; x = w; w = t;
    }

    __half *x16, *w16, *qkv, *probs;
    float *scores;
    cudaGetSymbolAddress((void**)&x16,    g_x16);
    cudaGetSymbolAddress((void**)&w16,    g_w16);
    cudaGetSymbolAddress((void**)&qkv,    g_qkv);
    cudaGetSymbolAddress((void**)&scores, g_scores);
    cudaGetSymbolAddress((void**)&probs,  g_probs);

    // 1) converts
    cvt_f2h<<<4096, 256>>>(x, x16, N_X);
    cvt_f2h<<<2048, 256>>>(w, w16, N_W);

    // 2) QKV projections: [16384,768] @ [768,768] for z=0..2
    {
        dim3 grid(Oo / 128, (Bb * Ss) / 128, 3);
        gemm_wmma<false, true><<<grid, 256>>>(
            x16, w16, qkv,
            Bb * Ss, Oo, Dd, Dd, Oo, Oo, 1.0f,
            (size_t)0, (size_t)Dd * Oo, N_QKV);
    }

    // 3) scores = scale * Q @ K^T, per batch
    {
        dim3 grid(Ss / 128, Ss / 128, Bb);
        gemm_wmma<true, false><<<grid, 256>>>(
            qkv /*Q*/, qkv + N_QKV /*K*/, scores,
            Ss, Ss, Dd, Dd, Dd, Ss, SCALE,
            (size_t)Ss * Oo, (size_t)Ss * Oo, (size_t)Ss * Ss);
    }

    // 4) softmax rows
    softmax_rows<<<Bb * Ss, 256>>>(scores, probs);

    // 5) out = probs @ V, per batch, fp32 straight to d_out
    {
        dim3 grid(Oo / 128, Ss / 128, Bb);
        gemm_wmma<false, false><<<grid, 256>>>(
            probs, qkv + 2 * N_QKV, d_out,
            Ss, Oo, Ss, Ss, Oo, Oo, 1.0f,
            (size_t)Ss * Ss, (size_t)Ss * Oo, (size_t)Ss * Oo);
    }
}

// round 2
// speedup vs baseline: 1.1197x; 1.1197x over previous
#include <cuda_runtime.h>
#include <cuda_fp16.h>
#include <mma.h>
#include <cstdint>

using namespace nvcuda;

// Problem shape (fixed by the dataset)
#define Bb 8
#define Ss 2048
#define Dd 768
#define Oo 768
constexpr float SCALE = 0.125f;  // 1/sqrt(64), hardcoded in reference

constexpr size_t N_X   = (size_t)Bb * Ss * Dd;
constexpr size_t N_W   = (size_t)3 * Dd * Oo;
constexpr size_t N_QKV = (size_t)Bb * Ss * Oo;
constexpr size_t N_SC  = (size_t)Bb * Ss * Ss;

// Scratch (static device globals — no runtime allocation)
__device__ __half g_x16[N_X];
__device__ __half g_w16[N_W];
__device__ __half g_qkv[3 * N_QKV];   // Q | K | V, fp16
__device__ float  g_scores[N_SC];     // QK^T * scale, fp32
__device__ __half g_probs[N_SC];      // softmax(QK^T), fp16

// ---------------------------------------------------------------------------
// cp.async helpers
// ---------------------------------------------------------------------------
__device__ __forceinline__ void cp16(void* smem_dst, const void* gmem_src) {
    uint32_t s = (uint32_t)__cvta_generic_to_shared(smem_dst);
    asm volatile("cp.async.cg.shared.global [%0], [%1], 16;\n" :: "r"(s), "l"(gmem_src));
}
__device__ __forceinline__ void cp_commit() {
    asm volatile("cp.async.commit_group;\n" ::);
}
template <int N>
__device__ __forceinline__ void cp_wait() {
    asm volatile("cp.async.wait_group %0;\n" :: "n"(N));
}

// ---------------------------------------------------------------------------
// fp32 -> fp16 convert
// ---------------------------------------------------------------------------
__global__ void cvt_f2h(const float* __restrict__ in, __half* __restrict__ out, size_t n) {
    size_t i = (size_t)blockIdx.x * blockDim.x + threadIdx.x;
    size_t stride = (size_t)gridDim.x * blockDim.x;
    for (; i < n; i += stride) out[i] = __float2half(in[i]);
}

// ---------------------------------------------------------------------------
// Pipelined WMMA GEMM:  C = scale * A @ op(B)
//   Block tile 128x256x32, 3-stage cp.async pipeline, 8 warps, warp tile 64x64.
//   A: [M,K] fp16 row-major (lda)
//   B: BT=false -> [K,N] row-major (ldb);  BT=true -> [N,K] row-major (B^T used)
//   C: HALF_OUT ? fp16 : fp32, row-major (ldc). blockIdx.z batches via strides.
// ---------------------------------------------------------------------------
constexpr int BM = 128, BN = 256, BK = 32, STAGES = 3;
constexpr int APAD = 8, BPAD = 8;
constexpr int A_STRIDE = BK + APAD;                      // 40 halves / row
constexpr int A_STAGE  = BM * A_STRIDE;                  // halves per stage

template <bool BT>
struct BDims {
    static constexpr int ROWS = BT ? BN : BK;
    static constexpr int COLS = BT ? (BK + BPAD) : (BN + BPAD);
    static constexpr int STAGE = ROWS * COLS;
};

template <bool BT, bool HALF_OUT>
__global__ void __launch_bounds__(256)
gemm_cp(const __half* __restrict__ Ag, const __half* __restrict__ Bg,
        void* __restrict__ Cg,
        int K, int lda, int ldb, int ldc, float scale,
        size_t aStride, size_t bStride, size_t cStride)
{
    extern __shared__ __half smem[];
    __half* Aall = smem;                       // STAGES * A_STAGE
    __half* Ball = smem + STAGES * A_STAGE;    // STAGES * B_STAGE

    constexpr int B_STAGE = BDims<BT>::STAGE;
    constexpr int B_COLS  = BDims<BT>::COLS;

    const int tid    = threadIdx.x;
    const int warpId = tid >> 5;
    const int lane   = tid & 31;
    const int bm = blockIdx.y * BM;
    const int bn = blockIdx.x * BN;

    const __half* A  = Ag + (size_t)blockIdx.z * aStride;
    const __half* Bp = Bg + (size_t)blockIdx.z * bStride;

    const int warpM = warpId & 1;   // 2 x 64 = 128 rows
    const int warpN = warpId >> 1;  // 4 x 64 = 256 cols

    wmma::fragment<wmma::accumulator, 16, 16, 16, float> acc[4][4];
    #pragma unroll
    for (int fm = 0; fm < 4; fm++)
        #pragma unroll
        for (int fn = 0; fn < 4; fn++)
            wmma::fill_fragment(acc[fm][fn], 0.0f);

    // ---- stage loader ----
    auto load_stage = [&](int stage, int k0) {
        __half* As = Aall + stage * A_STAGE;
        __half* Bs = Ball + stage * B_STAGE;
        // A: 128x32 halves = 512 x 16B chunks, 2 per thread
        #pragma unroll
        for (int j = 0; j < 2; j++) {
            int c = tid + j * 256;
            int row = c >> 2;                 // / (BK/8)
            int col = (c & 3) << 3;
            cp16(&As[row * A_STRIDE + col],
                 &A[(size_t)(bm + row) * lda + k0 + col]);
        }
        if (!BT) {
            // B: 32x256 halves = 1024 chunks, 4 per thread
            #pragma unroll
            for (int j = 0; j < 4; j++) {
                int c = tid + j * 256;
                int row = c >> 5;             // / (BN/8)
                int col = (c & 31) << 3;
                cp16(&Bs[row * B_COLS + col],
                     &Bp[(size_t)(k0 + row) * ldb + bn + col]);
            }
        } else {
            // B: 256x32 halves = 1024 chunks, 4 per thread
            #pragma unroll
            for (int j = 0; j < 4; j++) {
                int c = tid + j * 256;
                int row = c >> 2;             // / (BK/8)
                int col = (c & 3) << 3;
                cp16(&Bs[row * B_COLS + col],
                     &Bp[(size_t)(bn + row) * ldb + k0 + col]);
            }
        }
    };

    const int kTiles = K / BK;

    // ---- prologue: issue STAGES-1 stages ----
    #pragma unroll
    for (int s = 0; s < STAGES - 1; s++) {
        load_stage(s, s * BK);
        cp_commit();
    }

    // ---- main loop ----
    for (int t = 0; t < kTiles; t++) {
        cp_wait<STAGES - 2>();
        __syncthreads();

        const int stage = t % STAGES;
        const __half* As = Aall + stage * A_STAGE;
        const __half* Bs = Ball + stage * B_STAGE;

        #pragma unroll
        for (int kk = 0; kk < BK; kk += 16) {
            wmma::fragment<wmma::matrix_a, 16, 16, 16, __half, wmma::row_major> af[4];
            #pragma unroll
            for (int fm = 0; fm < 4; fm++)
                wmma::load_matrix_sync(af[fm],
                    &As[(warpM * 64 + fm * 16) * A_STRIDE + kk], A_STRIDE);

            #pragma unroll
            for (int fn = 0; fn < 4; fn++) {
                if (!BT) {
                    wmma::fragment<wmma::matrix_b, 16, 16, 16, __half, wmma::row_major> bf;
                    wmma::load_matrix_sync(bf,
                        &Bs[kk * B_COLS + warpN * 64 + fn * 16], B_COLS);
                    #pragma unroll
                    for (int fm = 0; fm < 4; fm++)
                        wmma::mma_sync(acc[fm][fn], af[fm], bf, acc[fm][fn]);
                } else {
                    wmma::fragment<wmma::matrix_b, 16, 16, 16, __half, wmma::col_major> bf;
                    wmma::load_matrix_sync(bf,
                        &Bs[(warpN * 64 + fn * 16) * B_COLS + kk], B_COLS);
                    #pragma unroll
                    for (int fm = 0; fm < 4; fm++)
                        wmma::mma_sync(acc[fm][fn], af[fm], bf, acc[fm][fn]);
                }
            }
        }

        int tn = t + STAGES - 1;
        if (tn < kTiles) load_stage(tn % STAGES, tn * BK);
        cp_commit();
    }

    // ---- epilogue ----
    __syncthreads();   // done with pipeline buffers; reuse smem for staging

    #pragma unroll
    for (int fm = 0; fm < 4; fm++) {
        #pragma unroll
        for (int fn = 0; fn < 4; fn++) {
            #pragma unroll
            for (int e = 0; e < acc[fm][fn].num_elements; e++)
                acc[fm][fn].x[e] *= scale;

            int r0 = bm + warpM * 64 + fm * 16;
            int c0 = bn + warpN * 64 + fn * 16;

            if (!HALF_OUT) {
                float* Cf = (float*)Cg + (size_t)blockIdx.z * cStride;
                wmma::store_matrix_sync(&Cf[(size_t)r0 * ldc + c0], acc[fm][fn],
                                        ldc, wmma::mem_row_major);
            } else {
                float* stage = (float*)smem + warpId * 256;
                __half* Ch = (__half*)Cg + (size_t)blockIdx.z * cStride;
                wmma::store_matrix_sync(stage, acc[fm][fn], 16, wmma::mem_row_major);
                __syncwarp();
                int rr = lane >> 1;
                int cc = (lane & 1) * 8;
                __half tmp[8];
                #pragma unroll
                for (int j = 0; j < 8; j++)
                    tmp[j] = __float2half(stage[rr * 16 + cc + j]);
                *(float4*)&Ch[(size_t)(r0 + rr) * ldc + c0 + cc] = *(float4*)tmp;
                __syncwarp();
            }
        }
    }
}

// ---------------------------------------------------------------------------
// Row softmax: scores fp32 [rows x 2048] -> probs fp16
// ---------------------------------------------------------------------------
__device__ __forceinline__ float warpMax(float v) {
    #pragma unroll
    for (int o = 16; o; o >>= 1) v = fmaxf(v, __shfl_xor_sync(0xffffffffu, v, o));
    return v;
}
__device__ __forceinline__ float warpSum(float v) {
    #pragma unroll
    for (int o = 16; o; o >>= 1) v += __shfl_xor_sync(0xffffffffu, v, o);
    return v;
}

__global__ void __launch_bounds__(256)
softmax_rows(const float* __restrict__ s, __half* __restrict__ p)
{
    const size_t row = blockIdx.x;
    const float* sr = s + row * Ss;
    __half* pr = p + row * Ss;
    const int tid = threadIdx.x;
    const int warp = tid >> 5, lane = tid & 31;

    float vals[8];
    float mx = -3.0e38f;
    #pragma unroll
    for (int j = 0; j < 8; j++) {
        vals[j] = sr[tid + j * 256];
        mx = fmaxf(mx, vals[j]);
    }
    __shared__ float redm[8], reds[8];
    mx = warpMax(mx);
    if (lane == 0) redm[warp] = mx;
    __syncthreads();
    float m = redm[0];
    #pragma unroll
    for (int i = 1; i < 8; i++) m = fmaxf(m, redm[i]);

    float sum = 0.0f;
    #pragma unroll
    for (int j = 0; j < 8; j++) {
        vals[j] = __expf(vals[j] - m);
        sum += vals[j];
    }
    sum = warpSum(sum);
    if (lane == 0) reds[warp] = sum;
    __syncthreads();
    float tot = 0.0f;
    #pragma unroll
    for (int i = 0; i < 8; i++) tot += reds[i];
    float inv = 1.0f / tot;

    #pragma unroll
    for (int j = 0; j < 8; j++)
        pr[tid + j * 256] = __float2half(vals[j] * inv);
}

// ---------------------------------------------------------------------------
// Launch
// ---------------------------------------------------------------------------
extern "C" void kernel_launch(void* const* d_in, const int* in_sizes, int n_in,
                              void* d_out, int out_size)
{
    const float* x = (const float*)d_in[0];
    const float* w = (const float*)d_in[1];
    if (n_in >= 2 && in_sizes[0] == (int)N_W && in_sizes[1] == (int)N_X) {
        const float* t = x; x = w; w = t;
    }

    __half *x16, *w16, *qkv, *probs;
    float *scores;
    cudaGetSymbolAddress((void**)&x16,    g_x16);
    cudaGetSymbolAddress((void**)&w16,    g_w16);
    cudaGetSymbolAddress((void**)&qkv,    g_qkv);
    cudaGetSymbolAddress((void**)&scores, g_scores);
    cudaGetSymbolAddress((void**)&probs,  g_probs);

    constexpr int SMEM_BT = (int)(STAGES * (A_STAGE + BDims<true >::STAGE) * sizeof(__half)); // 92160
    constexpr int SMEM_BF = (int)(STAGES * (A_STAGE + BDims<false>::STAGE) * sizeof(__half)); // 81408

    cudaFuncSetAttribute(gemm_cp<false, true >, cudaFuncAttributeMaxDynamicSharedMemorySize, SMEM_BF);
    cudaFuncSetAttribute(gemm_cp<true,  false>, cudaFuncAttributeMaxDynamicSharedMemorySize, SMEM_BT);
    cudaFuncSetAttribute(gemm_cp<false, false>, cudaFuncAttributeMaxDynamicSharedMemorySize, SMEM_BF);

    // 1) converts
    cvt_f2h<<<4096, 256>>>(x, x16, N_X);
    cvt_f2h<<<2048, 256>>>(w, w16, N_W);

    // 2) QKV projections: [16384,768] @ [768,768] for z=0..2 -> fp16
    {
        dim3 grid(Oo / BN, (Bb * Ss) / BM, 3);
        gemm_cp<false, true><<<grid, 256, SMEM_BF>>>(
            x16, w16, qkv,
            Dd, Dd, Oo, Oo, 1.0f,
            (size_t)0, (size_t)Dd * Oo, N_QKV);
    }

    // 3) scores = scale * Q @ K^T, per batch -> fp32
    {
        dim3 grid(Ss / BN, Ss / BM, Bb);
        gemm_cp<true, false><<<grid, 256, SMEM_BT>>>(
            qkv /*Q*/, qkv + N_QKV /*K*/, scores,
            Dd, Dd, Dd, Ss, SCALE,
            (size_t)Ss * Oo, (size_t)Ss * Oo, (size_t)Ss * Ss);
    }

    // 4) softmax rows
    softmax_rows<<<Bb * Ss, 256>>>(scores, probs);

    // 5) out = probs @ V, per batch -> fp32 d_out
    {
        dim3 grid(Oo / BN, Ss / BM, Bb);
        gemm_cp<false, false><<<grid, 256, SMEM_BF>>>(
            probs, qkv + 2 * N_QKV, d_out,
            Ss, Ss, Oo, Oo, 1.0f,
            (size_t)Ss * Ss, (size_t)Ss * Oo, (size_t)Ss * Oo);
    }
}

// round 4
// speedup vs baseline: 1.4295x; 1.2767x over previous
#include <cuda_runtime.h>
#include <cuda_fp16.h>
#include <cstdint>

// Problem shape (fixed by the dataset)
#define Bb 8
#define Ss 2048
#define Dd 768
#define Oo 768
constexpr float SCALE = 0.125f;  // 1/sqrt(64), hardcoded in reference

constexpr size_t N_X   = (size_t)Bb * Ss * Dd;
constexpr size_t N_W   = (size_t)3 * Dd * Oo;
constexpr size_t N_QKV = (size_t)Bb * Ss * Oo;
constexpr size_t N_SC  = (size_t)Bb * Ss * Ss;

// Scratch (static device globals — no runtime allocation)
__device__ __half g_x16[N_X];         // x fp16 [B*S, D]
__device__ __half g_wT[N_W];          // W^T fp16 [3][O, D]
__device__ __half g_qkv[3 * N_QKV];   // Q | K | V fp16 [B*S, O]
__device__ __half g_vT[N_QKV];        // V^T fp16 [B][O, S]
__device__ float  g_scores[N_SC];     // QK^T * scale fp32
__device__ __half g_probs[N_SC];      // softmax fp16

// ---------------------------------------------------------------------------
// PTX helpers (base sm_103 ISA only: cp.async, ldmatrix, mma.sync)
// ---------------------------------------------------------------------------
__device__ __forceinline__ uint32_t smem_u32(const void* p) {
    return (uint32_t)__cvta_generic_to_shared(p);
}
__device__ __forceinline__ void cp16(uint32_t saddr, const void* gaddr) {
    asm volatile("cp.async.cg.shared.global [%0], [%1], 16;\n" :: "r"(saddr), "l"(gaddr));
}
__device__ __forceinline__ void cp_commit() {
    asm volatile("cp.async.commit_group;\n" ::: "memory");
}
__device__ __forceinline__ void cp_wait1() {
    asm volatile("cp.async.wait_group 1;\n" ::: "memory");
}

#define LDSM4(r0, r1, r2, r3, addr) \
    asm volatile("ldmatrix.sync.aligned.m8n8.x4.shared.b16 {%0,%1,%2,%3}, [%4];" \
                 : "=r"(r0), "=r"(r1), "=r"(r2), "=r"(r3) : "r"(addr))

#define MMA16816(d, a, b) \
    asm volatile("mma.sync.aligned.m16n8k16.row.col.f32.f16.f16.f32 " \
                 "{%0,%1,%2,%3},{%4,%5,%6,%7},{%8,%9},{%0,%1,%2,%3};" \
                 : "+f"((d)[0]), "+f"((d)[1]), "+f"((d)[2]), "+f"((d)[3]) \
                 : "r"((a)[0]), "r"((a)[1]), "r"((a)[2]), "r"((a)[3]), \
                   "r"((b)[0]), "r"((b)[1]))

// ---------------------------------------------------------------------------
// mma.sync GEMM:  C[M,N] = scale * A[M,K] @ B[N,K]^T  (both K-major fp16)
// Block 128x128x64, 3-stage cp.async, 8 warps (2x4), warp tile 64x32.
// smem: per stage A 16KB + B 16KB, swizzled (chunk ^ (row&7)) 128B rows.
// ---------------------------------------------------------------------------
constexpr int BM = 128, BN = 128, BK = 64, STAGES = 3;
constexpr int STAGE_BYTES = (BM + BN) * BK * 2;            // 32768
constexpr int SMEM_TOTAL  = STAGES * STAGE_BYTES;          // 98304

__device__ __forceinline__ uint32_t swz_addr(uint32_t base, int r, int khalf) {
    // row r (128B rows), khalf = half-index within row (multiple of 8 here)
    int chunk = khalf >> 3;
    return base + r * 128 + (uint32_t)((chunk ^ (r & 7)) << 4);
}

template <bool HALF_OUT>
__global__ void __launch_bounds__(256)
gemm_mma(const __half* __restrict__ Ag, const __half* __restrict__ Bg,
         void* __restrict__ Cg,
         int kTiles, int lda, int ldb, int ldc, float scale,
         size_t aStr, size_t bStr, size_t cStr)
{
    extern __shared__ __align__(1024) char smem[];
    const uint32_t sb = smem_u32(smem);
    const int tid  = threadIdx.x;
    const int wid  = tid >> 5;
    const int lane = tid & 31;
    const int bm = blockIdx.y * BM;
    const int bn = blockIdx.x * BN;
    const int warpM = wid & 1;    // 2 x 64 rows
    const int warpN = wid >> 1;   // 4 x 32 cols

    const __half* A = Ag + (size_t)blockIdx.z * aStr;
    const __half* B = Bg + (size_t)blockIdx.z * bStr;

    // ---- stage loader: A 128x64 + B 128x64 halves, swizzled ----
    auto load_stage = [&](int s, int k0) {
        uint32_t abase = sb + s * STAGE_BYTES;
        uint32_t bbase = abase + BM * BK * 2;
        #pragma unroll
        for (int j = 0; j < 4; j++) {
            int c = tid + j * 256;
            int r = c >> 3, cc = c & 7;
            cp16(abase + r * 128 + (uint32_t)((cc ^ (r & 7)) << 4),
                 &A[(size_t)(bm + r) * lda + k0 + cc * 8]);
        }
        #pragma unroll
        for (int j = 0; j < 4; j++) {
            int c = tid + j * 256;
            int r = c >> 3, cc = c & 7;
            cp16(bbase + r * 128 + (uint32_t)((cc ^ (r & 7)) << 4),
                 &B[(size_t)(bn + r) * ldb + k0 + cc * 8]);
        }
    };

    float acc[4][4][4];
    #pragma unroll
    for (int fm = 0; fm < 4; fm++)
        #pragma unroll
        for (int fn = 0; fn < 4; fn++)
            #pragma unroll
            for (int e = 0; e < 4; e++) acc[fm][fn][e] = 0.0f;

    uint32_t afr[2][4][4], bfr[2][4][2];

    // per-lane ldmatrix row/k offsets (constant across ksteps)
    const int a_r  = lane & 15;             // row within 16
    const int a_kh = (lane >> 4) << 3;      // 0 or 8 halves
    const int b_r  = ((lane >> 4) << 3) + (lane & 7);  // n within 16
    const int b_kh = ((lane >> 3) & 1) << 3;           // 0 or 8 halves

    // fetch fragments for k-step ks (k = ks*16) of stage s into buffer slot
    auto fetch = [&](int s, int ks, uint32_t af[4][4], uint32_t bf[4][2]) {
        uint32_t abase = sb + s * STAGE_BYTES;
        uint32_t bbase = abase + BM * BK * 2;
        int k0 = ks * 16;
        #pragma unroll
        for (int fm = 0; fm < 4; fm++) {
            uint32_t addr = swz_addr(abase, warpM * 64 + fm * 16 + a_r, k0 + a_kh);
            LDSM4(af[fm][0], af[fm][1], af[fm][2], af[fm][3], addr);
        }
        #pragma unroll
        for (int g = 0; g < 2; g++) {
            uint32_t addr = swz_addr(bbase, warpN * 32 + g * 16 + b_r, k0 + b_kh);
            uint32_t t0, t1, t2, t3;
            LDSM4(t0, t1, t2, t3, addr);
            bf[g * 2 + 0][0] = t0; bf[g * 2 + 0][1] = t1;
            bf[g * 2 + 1][0] = t2; bf[g * 2 + 1][1] = t3;
        }
    };

    // ---- prologue ----
    load_stage(0, 0);
    cp_commit();
    load_stage(1, BK);
    cp_commit();

    // ---- main loop ----
    for (int t = 0; t < kTiles; t++) {
        cp_wait1();
        __syncthreads();
        const int s = t % STAGES;

        fetch(s, 0, afr[0], bfr[0]);
        #pragma unroll
        for (int ks = 0; ks < 4; ks++) {
            if (ks < 3) fetch(s, ks + 1, afr[(ks + 1) & 1], bfr[(ks + 1) & 1]);
            const int cur = ks & 1;
            #pragma unroll
            for (int fm = 0; fm < 4; fm++)
                #pragma unroll
                for (int fn = 0; fn < 4; fn++)
                    MMA16816(acc[fm][fn], afr[cur][fm], bfr[cur][fn]);
        }

        if (t + 2 < kTiles) load_stage((t + 2) % STAGES, (t + 2) * BK);
        cp_commit();
    }

    // ---- epilogue ----
    const int er = bm + warpM * 64 + (lane >> 2);
    const int ec = bn + warpN * 32 + ((lane & 3) << 1);
    #pragma unroll
    for (int fm = 0; fm < 4; fm++) {
        #pragma unroll
        for (int fn = 0; fn < 4; fn++) {
            int r = er + fm * 16;
            int c = ec + fn * 8;
            if (!HALF_OUT) {
                float* Cf = (float*)Cg + (size_t)blockIdx.z * cStr;
                float2 v0, v1;
                v0.x = acc[fm][fn][0] * scale; v0.y = acc[fm][fn][1] * scale;
                v1.x = acc[fm][fn][2] * scale; v1.y = acc[fm][fn][3] * scale;
                *(float2*)&Cf[(size_t)r * ldc + c]       = v0;
                *(float2*)&Cf[(size_t)(r + 8) * ldc + c] = v1;
            } else {
                __half* Ch = (__half*)Cg + (size_t)blockIdx.z * cStr;
                __half2 h0 = __floats2half2_rn(acc[fm][fn][0] * scale, acc[fm][fn][1] * scale);
                __half2 h1 = __floats2half2_rn(acc[fm][fn][2] * scale, acc[fm][fn][3] * scale);
                *(__half2*)&Ch[(size_t)r * ldc + c]       = h0;
                *(__half2*)&Ch[(size_t)(r + 8) * ldc + c] = h1;
            }
        }
    }
}

// ---------------------------------------------------------------------------
// fp32 -> fp16 convert
// ---------------------------------------------------------------------------
__global__ void cvt_f2h(const float* __restrict__ in, __half* __restrict__ out, size_t n) {
    size_t i = (size_t)blockIdx.x * blockDim.x + threadIdx.x;
    size_t stride = (size_t)gridDim.x * blockDim.x;
    for (; i < n; i += stride) out[i] = __float2half(in[i]);
}

// W [3][D][O] fp32 -> W^T [3][O][D] fp16
__global__ void transpose_w(const float* __restrict__ w, __half* __restrict__ wt) {
    __shared__ __half tile[32][33];
    const int z  = blockIdx.z;
    const int d0 = blockIdx.y * 32;
    const int o0 = blockIdx.x * 32;
    const int tx = threadIdx.x, ty = threadIdx.y;
    const float* W  = w  + (size_t)z * Dd * Oo;
    __half*      WT = wt + (size_t)z * Dd * Oo;
    #pragma unroll
    for (int j = 0; j < 32; j += 8)
        tile[ty + j][tx] = __float2half(W[(size_t)(d0 + ty + j) * Oo + o0 + tx]);
    __syncthreads();
    #pragma unroll
    for (int j = 0; j < 32; j += 8)
        WT[(size_t)(o0 + ty + j) * Dd + d0 + tx] = tile[tx][ty + j];
}

// V [B][S][O] fp16 -> V^T [B][O][S] fp16
__global__ void transpose_v(const __half* __restrict__ v, __half* __restrict__ vt) {
    __shared__ __half tile[32][33];
    const int z  = blockIdx.z;
    const int s0 = blockIdx.x * 32;
    const int o0 = blockIdx.y * 32;
    const int tx = threadIdx.x, ty = threadIdx.y;
    const __half* V  = v  + (size_t)z * Ss * Oo;
    __half*       VT = vt + (size_t)z * Ss * Oo;
    #pragma unroll
    for (int j = 0; j < 32; j += 8)
        tile[ty + j][tx] = V[(size_t)(s0 + ty + j) * Oo + o0 + tx];
    __syncthreads();
    #pragma unroll
    for (int j = 0; j < 32; j += 8)
        VT[(size_t)(o0 + ty + j) * Ss + s0 + tx] = tile[tx][ty + j];
}

// ---------------------------------------------------------------------------
// Row softmax: scores fp32 [rows x 2048] -> probs fp16
// ---------------------------------------------------------------------------
__device__ __forceinline__ float warpMax(float v) {
    #pragma unroll
    for (int o = 16; o; o >>= 1) v = fmaxf(v, __shfl_xor_sync(0xffffffffu, v, o));
    return v;
}
__device__ __forceinline__ float warpSum(float v) {
    #pragma unroll
    for (int o = 16; o; o >>= 1) v += __shfl_xor_sync(0xffffffffu, v, o);
    return v;
}

__global__ void __launch_bounds__(256)
softmax_rows(const float* __restrict__ s, __half* __restrict__ p)
{
    const size_t row = blockIdx.x;
    const float* sr = s + row * Ss;
    __half* pr = p + row * Ss;
    const int tid = threadIdx.x;
    const int warp = tid >> 5, lane = tid & 31;

    float vals[8];
    float mx = -3.0e38f;
    #pragma unroll
    for (int j = 0; j < 8; j++) {
        vals[j] = sr[tid + j * 256];
        mx = fmaxf(mx, vals[j]);
    }
    __shared__ float redm[8], reds[8];
    mx = warpMax(mx);
    if (lane == 0) redm[warp] = mx;
    __syncthreads();
    float m = redm[0];
    #pragma unroll
    for (int i = 1; i < 8; i++) m = fmaxf(m, redm[i]);

    float sum = 0.0f;
    #pragma unroll
    for (int j = 0; j < 8; j++) {
        vals[j] = __expf(vals[j] - m);
        sum += vals[j];
    }
    sum = warpSum(sum);
    if (lane == 0) reds[warp] = sum;
    __syncthreads();
    float tot = 0.0f;
    #pragma unroll
    for (int i = 0; i < 8; i++) tot += reds[i];
    float inv = 1.0f / tot;

    #pragma unroll
    for (int j = 0; j < 8; j++)
        pr[tid + j * 256] = __float2half(vals[j] * inv);
}

// ---------------------------------------------------------------------------
// Launch
// ---------------------------------------------------------------------------
extern "C" void kernel_launch(void* const* d_in, const int* in_sizes, int n_in,
                              void* d_out, int out_size)
{
    const float* x = (const float*)d_in[0];
    const float* w = (const float*)d_in[1];
    if (n_in >= 2 && in_sizes[0] == (int)N_W && in_sizes[1] == (int)N_X) {
        const float* t = x; x = w; w = t;
    }

    __half *x16, *wT, *qkv, *vT, *probs;
    float *scores;
    cudaGetSymbolAddress((void**)&x16,    g_x16);
    cudaGetSymbolAddress((void**)&wT,     g_wT);
    cudaGetSymbolAddress((void**)&qkv,    g_qkv);
    cudaGetSymbolAddress((void**)&vT,     g_vT);
    cudaGetSymbolAddress((void**)&scores, g_scores);
    cudaGetSymbolAddress((void**)&probs,  g_probs);

    cudaFuncSetAttribute(gemm_mma<true >, cudaFuncAttributeMaxDynamicSharedMemorySize, SMEM_TOTAL);
    cudaFuncSetAttribute(gemm_mma<false>, cudaFuncAttributeMaxDynamicSharedMemorySize, SMEM_TOTAL);

    // 1) converts / weight transpose
    cvt_f2h<<<4096, 256>>>(x, x16, N_X);
    {
        dim3 grid(Oo / 32, Dd / 32, 3);
        transpose_w<<<grid, dim3(32, 8)>>>(w, wT);
    }

    // 2) QKV projections: [16384,768] = X @ (W^T)^T per z -> fp16
    {
        dim3 grid(Oo / BN, (Bb * Ss) / BM, 3);
        gemm_mma<true><<<grid, 256, SMEM_TOTAL>>>(
            x16, wT, qkv,
            Dd / BK, Dd, Dd, Oo, 1.0f,
            (size_t)0, (size_t)Dd * Oo, N_QKV);
    }

    // 3) V^T for the AV GEMM
    {
        dim3 grid(Ss / 32, Oo / 32, Bb);
        transpose_v<<<grid, dim3(32, 8)>>>(qkv + 2 * N_QKV, vT);
    }

    // 4) scores = scale * Q @ K^T per batch -> fp32
    {
        dim3 grid(Ss / BN, Ss / BM, Bb);
        gemm_mma<false><<<grid, 256, SMEM_TOTAL>>>(
            qkv, qkv + N_QKV, scores,
            Dd / BK, Dd, Dd, Ss, SCALE,
            (size_t)Ss * Oo, (size_t)Ss * Oo, (size_t)Ss * Ss);
    }

    // 5) softmax rows
    softmax_rows<<<Bb * Ss, 256>>>(scores, probs);

    // 6) out = P @ (V^T)^T per batch -> fp32 d_out
    {
        dim3 grid(Oo / BN, Ss / BM, Bb);
        gemm_mma<false><<<grid, 256, SMEM_TOTAL>>>(
            probs, vT, d_out,
            Ss / BK, Ss, Ss, Oo, 1.0f,
            (size_t)Ss * Ss, (size_t)Oo * Ss, (size_t)Ss * Oo);
    }
}